// round 2
// baseline (speedup 1.0000x reference)
#include <cuda_runtime.h>

#define NN 50000
#define EE 800000

// ---- scratch (static device memory; allocation-free per harness rules) ----
__device__ float d_x[NN * 32];
__device__ float d_id[NN * 64];
__device__ float d_h1[NN * 256];
__device__ float d_as1[NN * 4];
__device__ float d_ad1[NN * 4];
__device__ float d_den1[NN * 4];
__device__ float d_acc1[NN * 256];
__device__ float d_hmid[NN * 256];
__device__ float d_h2[NN * 64];
__device__ float d_as2[NN];
__device__ float d_ad2[NN];
__device__ float d_den2[NN];
__device__ float d_acc2[NN * 64];
__device__ float d_pool[64];
__device__ int d_is64;

__device__ __forceinline__ float wredsum(float v) {
#pragma unroll
    for (int o = 16; o; o >>= 1) v += __shfl_xor_sync(0xffffffffu, v, o);
    return v;
}
__device__ __forceinline__ float lrelu(float x) { return x > 0.f ? x : 0.2f * x; }
__device__ __forceinline__ float elu1(float x) { return x > 0.f ? x : expm1f(x); }

// K0: detect edge_index dtype. int64 little-endian with values in [0,50000)
// has all-zero high words; int32 has random values in odd slots.
__global__ void k_detect(const int* __restrict__ w) {
    if (threadIdx.x == 0) {
        int all0 = 1;
#pragma unroll 1
        for (int i = 0; i < 64; i++)
            if (w[2 * i + 1] != 0) { all0 = 0; break; }
        d_is64 = all0;
    }
}

// K1: node encoder: [N,4] -> Linear(4,32) -> relu -> LN(32). 8 nodes/block, 32 thr/node.
__global__ void k_encode(const float* __restrict__ pos, const float* __restrict__ deg,
                         const float* __restrict__ W, const float* __restrict__ b,
                         const float* __restrict__ g, const float* __restrict__ be) {
    if (blockIdx.x == 0 && threadIdx.x < 64) d_pool[threadIdx.x] = 0.f;
    int node = blockIdx.x * 8 + (threadIdx.x >> 5);
    int c = threadIdx.x & 31;
    float p0 = pos[node * 3], p1 = pos[node * 3 + 1], p2 = pos[node * 3 + 2], dgr = deg[node];
    float v = fmaf(p0, W[c], fmaf(p1, W[32 + c], fmaf(p2, W[64 + c], fmaf(dgr, W[96 + c], b[c]))));
    v = fmaxf(v, 0.f);
    float m = wredsum(v) * (1.f / 32.f);
    float d = v - m;
    float var = wredsum(d * d) * (1.f / 32.f);
    d_x[node * 32 + c] = d * rsqrtf(var + 1e-5f) * g[c] + be[c];
}

// K_id: identity = x @ proj_w + proj_b. 4 nodes/block, 64 thr/node.
__global__ void k_identity(const float* __restrict__ pw, const float* __restrict__ pb) {
    __shared__ float xs[4][32];
    int t = threadIdx.x;
    int n0 = blockIdx.x * 4;
    if (t < 128) xs[t >> 5][t & 31] = d_x[(n0 + (t >> 5)) * 32 + (t & 31)];
    __syncthreads();
    int grp = t >> 6, c = t & 63;
    float a = pb[c];
#pragma unroll
    for (int k = 0; k < 32; k++) a = fmaf(xs[grp][k], pw[k * 64 + c], a);
    d_id[(n0 + grp) * 64 + c] = a;
}

// K2: gat1 linear h1 = x@W [N,256], attention scalars a_s/a_d [N,4],
//     and self-loop init of denom1 / acc1 (no memset needed).
__global__ void k_gat1_lin(const float* __restrict__ W, const float* __restrict__ as_,
                           const float* __restrict__ ad_) {
    __shared__ float xs[4][32];
    __shared__ float rs[8], rd[8], sex[4];
    int t = threadIdx.x, lane = t & 31, w = t >> 5;
    int n0 = blockIdx.x * 4;
    if (t < 128) xs[t >> 5][t & 31] = d_x[(n0 + (t >> 5)) * 32 + (t & 31)];
    float wreg[32];
#pragma unroll
    for (int k = 0; k < 32; k++) wreg[k] = W[k * 256 + t];
    float ats = as_[t], atd = ad_[t];
    __syncthreads();
    for (int nn = 0; nn < 4; nn++) {
        float hv = 0.f;
#pragma unroll
        for (int k = 0; k < 32; k++) hv = fmaf(xs[nn][k], wreg[k], hv);
        float ps = wredsum(hv * ats);
        float pd = wredsum(hv * atd);
        if (lane == 0) { rs[w] = ps; rd[w] = pd; }
        __syncthreads();
        int n = n0 + nn;
        if (t < 4) {
            float a = rs[2 * t] + rs[2 * t + 1];
            float b = rd[2 * t] + rd[2 * t + 1];
            d_as1[n * 4 + t] = a;
            d_ad1[n * 4 + t] = b;
            float ex = expf(lrelu(a + b));
            d_den1[n * 4 + t] = ex;
            sex[t] = ex;
        }
        __syncthreads();
        d_h1[n * 256 + t] = hv;
        d_acc1[n * 256 + t] = sex[t >> 6] * hv;
        __syncthreads();
    }
}

// K3: GAT1 edge pass. One warp per edge; fused numerator+denominator atomics.
__global__ void k_edge1(const int* __restrict__ eiw) {
    int e = blockIdx.x * 8 + (threadIdx.x >> 5);
    int lane = threadIdx.x & 31;
    int is64 = d_is64;
    int src, dst;
    if (is64) { src = eiw[2 * e]; dst = eiw[2 * (EE + e)]; }
    else      { src = eiw[e];     dst = eiw[EE + e]; }
    src = min(max(src, 0), NN - 1);
    dst = min(max(dst, 0), NN - 1);
    float4 a4 = *(const float4*)&d_as1[src * 4];
    float4 b4 = *(const float4*)&d_ad1[dst * 4];
    float ex0 = expf(lrelu(a4.x + b4.x));
    float ex1 = expf(lrelu(a4.y + b4.y));
    float ex2 = expf(lrelu(a4.z + b4.z));
    float ex3 = expf(lrelu(a4.w + b4.w));
    const float4* hrow = (const float4*)&d_h1[src * 256];
    float* arow = &d_acc1[dst * 256];
#pragma unroll
    for (int half = 0; half < 2; half++) {
        int idx = half * 32 + lane;
        float4 hv = hrow[idx];
        float eh = (half == 0) ? ((lane < 16) ? ex0 : ex1) : ((lane < 16) ? ex2 : ex3);
        atomicAdd(arow + idx * 4 + 0, eh * hv.x);
        atomicAdd(arow + idx * 4 + 1, eh * hv.y);
        atomicAdd(arow + idx * 4 + 2, eh * hv.z);
        atomicAdd(arow + idx * 4 + 3, eh * hv.w);
    }
    if (lane < 4) {
        float e4 = lane == 0 ? ex0 : lane == 1 ? ex1 : lane == 2 ? ex2 : ex3;
        atomicAdd(&d_den1[dst * 4 + lane], e4);
    }
}

// K4: normalize GAT1, + bias, LN(256), ELU -> hmid.
__global__ void k_gat1_post(const float* __restrict__ bias, const float* __restrict__ g,
                            const float* __restrict__ b2) {
    int n = blockIdx.x, t = threadIdx.x, lane = t & 31, w = t >> 5;
    __shared__ float rs[8], rq[8];
    float den = d_den1[n * 4 + (t >> 6)] + 1e-16f;
    float v = d_acc1[n * 256 + t] / den + bias[t];
    float s = wredsum(v);
    float q = wredsum(v * v);
    if (lane == 0) { rs[w] = s; rq[w] = q; }
    __syncthreads();
    float S = 0.f, Q = 0.f;
#pragma unroll
    for (int i = 0; i < 8; i++) { S += rs[i]; Q += rq[i]; }
    float m = S * (1.f / 256.f);
    float var = Q * (1.f / 256.f) - m * m;
    float y = (v - m) * rsqrtf(var + 1e-5f) * g[t] + b2[t];
    d_hmid[n * 256 + t] = elu1(y);
}

// K5: gat2 linear h2 = hmid @ W(256,64), attention scalars, self-loop init.
__global__ void k_gat2_lin(const float* __restrict__ W, const float* __restrict__ as_,
                           const float* __restrict__ ad_) {
    int n = blockIdx.x, t = threadIdx.x, lane = t & 31;
    __shared__ float sh[256];
    __shared__ float red[256];
    __shared__ float ss[2], sd[2], sexs;
    sh[t] = d_hmid[n * 256 + t];
    __syncthreads();
    int c = t & 63, part = t >> 6;
    float p = 0.f;
#pragma unroll 8
    for (int k = 0; k < 64; k++) p = fmaf(sh[part * 64 + k], W[(part * 64 + k) * 64 + c], p);
    red[t] = p;
    __syncthreads();
    float h2 = 0.f;
    if (t < 64) {
        h2 = red[c] + red[64 + c] + red[128 + c] + red[192 + c];
        d_h2[n * 64 + c] = h2;
        float ps = wredsum(h2 * as_[c]);
        float pd = wredsum(h2 * ad_[c]);
        if (lane == 0) { ss[t >> 5] = ps; sd[t >> 5] = pd; }
    }
    __syncthreads();
    if (t == 0) {
        float a = ss[0] + ss[1], b = sd[0] + sd[1];
        d_as2[n] = a;
        d_ad2[n] = b;
        float ex = expf(lrelu(a + b));
        d_den2[n] = ex;
        sexs = ex;
    }
    __syncthreads();
    if (t < 64) d_acc2[n * 64 + c] = sexs * h2;
}

// K6: GAT2 edge pass. Warp per edge, 2 channels/lane.
__global__ void k_edge2(const int* __restrict__ eiw) {
    int e = blockIdx.x * 8 + (threadIdx.x >> 5);
    int lane = threadIdx.x & 31;
    int is64 = d_is64;
    int src, dst;
    if (is64) { src = eiw[2 * e]; dst = eiw[2 * (EE + e)]; }
    else      { src = eiw[e];     dst = eiw[EE + e]; }
    src = min(max(src, 0), NN - 1);
    dst = min(max(dst, 0), NN - 1);
    float ex = expf(lrelu(d_as2[src] + d_ad2[dst]));
    float2 hv = ((const float2*)&d_h2[src * 64])[lane];
    atomicAdd(&d_acc2[dst * 64 + lane * 2], ex * hv.x);
    atomicAdd(&d_acc2[dst * 64 + lane * 2 + 1], ex * hv.y);
    if (lane == 0) atomicAdd(&d_den2[dst], ex);
}

// K7: normalize GAT2, + bias, LN(64), + identity, ELU, block-pool into d_pool.
__global__ void k_gat2_post(const float* __restrict__ bias, const float* __restrict__ g,
                            const float* __restrict__ b2) {
    int t = threadIdx.x, lane = t & 31, w = t >> 5, grp = t >> 6, c = t & 63;
    int n = blockIdx.x * 4 + grp;
    __shared__ float rs[8], rq[8], spool[64];
    if (t < 64) spool[t] = 0.f;
    float v = d_acc2[n * 64 + c] / (d_den2[n] + 1e-16f) + bias[c];
    float s = wredsum(v);
    float q = wredsum(v * v);
    if (lane == 0) { rs[w] = s; rq[w] = q; }
    __syncthreads();
    float S = rs[grp * 2] + rs[grp * 2 + 1];
    float Q = rq[grp * 2] + rq[grp * 2 + 1];
    float m = S * (1.f / 64.f);
    float var = Q * (1.f / 64.f) - m * m;
    float y = (v - m) * rsqrtf(var + 1e-5f) * g[c] + b2[c] + d_id[n * 64 + c];
    float h = elu1(y);
    atomicAdd(&spool[c], h);
    __syncthreads();
    if (t < 64) atomicAdd(&d_pool[t], spool[t]);
}

// K8: traffic encoder + fusion + final LN -> out[1,256]. Single block.
__global__ void k_final(const float* __restrict__ traffic, const float* __restrict__ trw,
                        const float* __restrict__ trb, const float* __restrict__ trg,
                        const float* __restrict__ trbe, const float* __restrict__ fuw,
                        const float* __restrict__ fub, const float* __restrict__ fug,
                        const float* __restrict__ fube, float* __restrict__ out) {
    int t = threadIdx.x, lane = t & 31, w = t >> 5;
    __shared__ float comb[96];
    __shared__ float rs[8], rq[8];
    if (t < 64) comb[t] = d_pool[t] * (1.f / (float)NN);
    if (t >= 128 && t < 160) {
        int c = t - 128;
        float v = trb[c];
#pragma unroll
        for (int k = 0; k < 5; k++) v = fmaf(traffic[k], trw[k * 32 + c], v);
        v = fmaxf(v, 0.f);
        float m = wredsum(v) * (1.f / 32.f);
        float d = v - m;
        float var = wredsum(d * d) * (1.f / 32.f);
        comb[64 + c] = d * rsqrtf(var + 1e-5f) * trg[c] + trbe[c];
    }
    __syncthreads();
    float o = fub[t];
#pragma unroll 8
    for (int k = 0; k < 96; k++) o = fmaf(comb[k], fuw[k * 256 + t], o);
    o = fmaxf(o, 0.f);
    float s = wredsum(o);
    float q = wredsum(o * o);
    if (lane == 0) { rs[w] = s; rq[w] = q; }
    __syncthreads();
    float S = 0.f, Q = 0.f;
#pragma unroll
    for (int i = 0; i < 8; i++) { S += rs[i]; Q += rq[i]; }
    float m = S * (1.f / 256.f);
    float var = Q * (1.f / 256.f) - m * m;
    out[t] = (o - m) * rsqrtf(var + 1e-5f) * fug[t] + fube[t];
}

extern "C" void kernel_launch(void* const* d_in, const int* in_sizes, int n_in,
                              void* d_out, int out_size) {
    // Resolve input ordering: setup_inputs dict order has edge_index (2*E elements) at slot 3;
    // reference() signature order has it last.
    bool dictOrder = (n_in > 3 && in_sizes[3] == 2 * EE);
    int ix[30];
    if (dictOrder) {
        for (int i = 0; i < 30; i++) ix[i] = i;
    } else {
        ix[0] = 0; ix[1] = 1; ix[2] = 2; ix[3] = n_in - 1;
        for (int i = 4; i < 30; i++) ix[i] = i - 1;
    }
    const float* pos    = (const float*)d_in[ix[0]];
    const float* deg    = (const float*)d_in[ix[1]];
    const float* tr     = (const float*)d_in[ix[2]];
    const int*   eiw    = (const int*)d_in[ix[3]];
    const float* enc_w  = (const float*)d_in[ix[4]];
    const float* enc_b  = (const float*)d_in[ix[5]];
    const float* enc_g  = (const float*)d_in[ix[6]];
    const float* enc_be = (const float*)d_in[ix[7]];
    const float* g1w    = (const float*)d_in[ix[8]];
    const float* g1as   = (const float*)d_in[ix[9]];
    const float* g1ad   = (const float*)d_in[ix[10]];
    const float* g1b    = (const float*)d_in[ix[11]];
    const float* n1g    = (const float*)d_in[ix[12]];
    const float* n1b    = (const float*)d_in[ix[13]];
    const float* pw     = (const float*)d_in[ix[14]];
    const float* pb     = (const float*)d_in[ix[15]];
    const float* g2w    = (const float*)d_in[ix[16]];
    const float* g2as   = (const float*)d_in[ix[17]];
    const float* g2ad   = (const float*)d_in[ix[18]];
    const float* g2b    = (const float*)d_in[ix[19]];
    const float* n2g    = (const float*)d_in[ix[20]];
    const float* n2b    = (const float*)d_in[ix[21]];
    const float* trw    = (const float*)d_in[ix[22]];
    const float* trb    = (const float*)d_in[ix[23]];
    const float* trg    = (const float*)d_in[ix[24]];
    const float* trbe   = (const float*)d_in[ix[25]];
    const float* fuw    = (const float*)d_in[ix[26]];
    const float* fub    = (const float*)d_in[ix[27]];
    const float* fug    = (const float*)d_in[ix[28]];
    const float* fube   = (const float*)d_in[ix[29]];

    k_detect<<<1, 32>>>(eiw);
    k_encode<<<NN / 8, 256>>>(pos, deg, enc_w, enc_b, enc_g, enc_be);
    k_identity<<<NN / 4, 256>>>(pw, pb);
    k_gat1_lin<<<NN / 4, 256>>>(g1w, g1as, g1ad);
    k_edge1<<<EE / 8, 256>>>(eiw);
    k_gat1_post<<<NN, 256>>>(g1b, n1g, n1b);
    k_gat2_lin<<<NN, 256>>>(g2w, g2as, g2ad);
    k_edge2<<<EE / 8, 256>>>(eiw);
    k_gat2_post<<<NN / 4, 256>>>(g2b, n2g, n2b);
    k_final<<<1, 256>>>(tr, trw, trb, trg, trbe, fuw, fub, fug, fube, (float*)d_out);
}

// round 3
// speedup vs baseline: 1.3652x; 1.3652x over previous
#include <cuda_runtime.h>

#define NN 50000
#define EE 800000
#define FULL 0xffffffffu

// ---- scratch (static device memory) ----
__device__ __align__(16) float d_x[NN * 32];
__device__ __align__(16) float d_id[NN * 64];
__device__ __align__(16) float d_h1[NN * 256];
__device__ __align__(16) float d_as1[NN * 4];
__device__ __align__(16) float d_ad1[NN * 4];
__device__ __align__(16) float d_hmid[NN * 256];
__device__ __align__(16) float d_h2[NN * 64];
__device__ __align__(16) float d_wt[64 * 256];
__device__ float d_as2[NN];
__device__ float d_ad2[NN];
__device__ float d_pool[64];
__device__ int d_deg[NN];
__device__ int d_off[NN + 1];
__device__ int d_fill[NN];
__device__ int d_csrc[EE];
__device__ int d_is64;

__device__ __forceinline__ float wredsum(float v) {
#pragma unroll
    for (int o = 16; o; o >>= 1) v += __shfl_xor_sync(FULL, v, o);
    return v;
}
__device__ __forceinline__ float lrelu(float x) { return x > 0.f ? x : 0.2f * x; }
__device__ __forceinline__ float elu1(float x) { return x > 0.f ? x : expm1f(x); }

// K0: detect edge_index dtype (int64 values < 50000 -> high words all zero).
__global__ void k_detect(const int* __restrict__ w) {
    if (threadIdx.x == 0) {
        int all0 = 1;
#pragma unroll 1
        for (int i = 0; i < 64; i++)
            if (w[2 * i + 1] != 0) { all0 = 0; break; }
        d_is64 = all0;
    }
}

__global__ void k_zero() {
    int i = blockIdx.x * 256 + threadIdx.x;
    if (i < NN) d_deg[i] = 0;
    if (i < 64) d_pool[i] = 0.f;
}

__global__ void k_hist(const int* __restrict__ eiw) {
    int e = blockIdx.x * 256 + threadIdx.x;
    int dst = d_is64 ? eiw[2 * (EE + e)] : eiw[EE + e];
    dst = min(max(dst, 0), NN - 1);
    atomicAdd(&d_deg[dst], 1);
}

// exclusive scan of d_deg -> d_off, d_fill. Single block of 1024.
__global__ void k_scan() {
    __shared__ int warpsum[32];
    __shared__ int carry;
    int t = threadIdx.x, lane = t & 31, wid = t >> 5;
    if (t == 0) carry = 0;
    __syncthreads();
    for (int base = 0; base < NN; base += 1024) {
        int i = base + t;
        int v = (i < NN) ? d_deg[i] : 0;
        int x = v;
#pragma unroll
        for (int o = 1; o < 32; o <<= 1) {
            int y = __shfl_up_sync(FULL, x, o);
            if (lane >= o) x += y;
        }
        if (lane == 31) warpsum[wid] = x;
        __syncthreads();
        if (t < 32) {
            int s = warpsum[t];
#pragma unroll
            for (int o = 1; o < 32; o <<= 1) {
                int y = __shfl_up_sync(FULL, s, o);
                if (t >= o) s += y;
            }
            warpsum[t] = s;
        }
        __syncthreads();
        int incl = x + (wid > 0 ? warpsum[wid - 1] : 0) + carry;
        if (i < NN) { d_off[i] = incl - v; d_fill[i] = incl - v; }
        __syncthreads();
        if (t == 1023) carry = incl;
        __syncthreads();
    }
    if (t == 0) d_off[NN] = EE;
}

__global__ void k_scatter(const int* __restrict__ eiw) {
    int e = blockIdx.x * 256 + threadIdx.x;
    int src, dst;
    if (d_is64) { src = eiw[2 * e]; dst = eiw[2 * (EE + e)]; }
    else        { src = eiw[e];     dst = eiw[EE + e]; }
    src = min(max(src, 0), NN - 1);
    dst = min(max(dst, 0), NN - 1);
    int pos = atomicAdd(&d_fill[dst], 1);
    d_csrc[pos] = src;
}

// K1: node encoder: Linear(4,32)+relu+LN(32). 8 nodes/block.
__global__ void k_encode(const float* __restrict__ pos, const float* __restrict__ deg,
                         const float* __restrict__ W, const float* __restrict__ b,
                         const float* __restrict__ g, const float* __restrict__ be) {
    int node = blockIdx.x * 8 + (threadIdx.x >> 5);
    int c = threadIdx.x & 31;
    float p0 = pos[node * 3], p1 = pos[node * 3 + 1], p2 = pos[node * 3 + 2], dgr = deg[node];
    float v = fmaf(p0, W[c], fmaf(p1, W[32 + c], fmaf(p2, W[64 + c], fmaf(dgr, W[96 + c], b[c]))));
    v = fmaxf(v, 0.f);
    float m = wredsum(v) * (1.f / 32.f);
    float d = v - m;
    float var = wredsum(d * d) * (1.f / 32.f);
    d_x[node * 32 + c] = d * rsqrtf(var + 1e-5f) * g[c] + be[c];
}

// identity = x @ proj_w + proj_b.
__global__ void k_identity(const float* __restrict__ pw, const float* __restrict__ pb) {
    __shared__ float xs[4][32];
    int t = threadIdx.x;
    int n0 = blockIdx.x * 4;
    if (t < 128) xs[t >> 5][t & 31] = d_x[(n0 + (t >> 5)) * 32 + (t & 31)];
    __syncthreads();
    int grp = t >> 6, c = t & 63;
    float a = pb[c];
#pragma unroll
    for (int k = 0; k < 32; k++) a = fmaf(xs[grp][k], pw[k * 64 + c], a);
    d_id[(n0 + grp) * 64 + c] = a;
}

// K2: gat1 linear h1 = x@W, attention scalars as1/ad1. 16 nodes/block.
__global__ void k_gat1_lin(const float* __restrict__ W, const float* __restrict__ as_,
                           const float* __restrict__ ad_) {
    __shared__ float xs[16][32];
    __shared__ float rs[8], rd[8];
    int t = threadIdx.x, lane = t & 31, w = t >> 5;
    int n0 = blockIdx.x * 16;
    for (int i = t; i < 512; i += 256) xs[i >> 5][i & 31] = d_x[n0 * 32 + i];
    float wreg[32];
#pragma unroll
    for (int k = 0; k < 32; k++) wreg[k] = W[k * 256 + t];
    float ats = as_[t], atd = ad_[t];
    __syncthreads();
#pragma unroll 1
    for (int nn = 0; nn < 16; nn++) {
        float hv = 0.f;
#pragma unroll
        for (int k = 0; k < 32; k++) hv = fmaf(xs[nn][k], wreg[k], hv);
        float ps = wredsum(hv * ats);
        float pd = wredsum(hv * atd);
        if (lane == 0) { rs[w] = ps; rd[w] = pd; }
        __syncthreads();
        int n = n0 + nn;
        if (t < 4) {
            d_as1[n * 4 + t] = rs[2 * t] + rs[2 * t + 1];
            d_ad1[n * 4 + t] = rd[2 * t] + rd[2 * t + 1];
        }
        d_h1[n * 256 + t] = hv;
        __syncthreads();
    }
}

// K3: GAT1 fused aggregate + normalize + bias + LN(256) + ELU. Warp per node.
__global__ void k_agg1(const float* __restrict__ bias, const float* __restrict__ g,
                       const float* __restrict__ b2) {
    int lane = threadIdx.x & 31;
    int n = blockIdx.x * 8 + (threadIdx.x >> 5);
    int hA = lane >> 4;  // head of channels 4*lane..4*lane+3; second half head = 2+hA

    float ad_l = d_ad1[n * 4 + (lane & 3)];
    const float4* h4 = (const float4*)d_h1;

    // self-loop init
    float ex = expf(lrelu(d_as1[n * 4 + (lane & 3)] + ad_l));
    float exA = __shfl_sync(FULL, ex, hA);
    float exB = __shfl_sync(FULL, ex, 2 + hA);
    float4 hv0 = h4[n * 64 + lane], hv1 = h4[n * 64 + 32 + lane];
    float4 a0 = make_float4(exA * hv0.x, exA * hv0.y, exA * hv0.z, exA * hv0.w);
    float4 a1 = make_float4(exB * hv1.x, exB * hv1.y, exB * hv1.z, exB * hv1.w);
    float denA = exA, denB = exB;

    int s = d_off[n], e = d_off[n + 1];
    int srcN = (s < e) ? d_csrc[s] : 0;
#pragma unroll 1
    for (int i = s; i < e; i++) {
        int src = srcN;
        if (i + 1 < e) srcN = d_csrc[i + 1];
        float asv = d_as1[src * 4 + (lane & 3)];
        float exe = expf(lrelu(asv + ad_l));
        float eA = __shfl_sync(FULL, exe, hA);
        float eB = __shfl_sync(FULL, exe, 2 + hA);
        float4 v0 = h4[src * 64 + lane];
        float4 v1 = h4[src * 64 + 32 + lane];
        a0.x = fmaf(eA, v0.x, a0.x); a0.y = fmaf(eA, v0.y, a0.y);
        a0.z = fmaf(eA, v0.z, a0.z); a0.w = fmaf(eA, v0.w, a0.w);
        a1.x = fmaf(eB, v1.x, a1.x); a1.y = fmaf(eB, v1.y, a1.y);
        a1.z = fmaf(eB, v1.z, a1.z); a1.w = fmaf(eB, v1.w, a1.w);
        denA += eA; denB += eB;
    }
    float rA = 1.f / (denA + 1e-16f), rB = 1.f / (denB + 1e-16f);
    const float4* bi4 = (const float4*)bias;
    float4 bb0 = bi4[lane], bb1 = bi4[32 + lane];
    float4 v0 = make_float4(a0.x * rA + bb0.x, a0.y * rA + bb0.y,
                            a0.z * rA + bb0.z, a0.w * rA + bb0.w);
    float4 v1 = make_float4(a1.x * rB + bb1.x, a1.y * rB + bb1.y,
                            a1.z * rB + bb1.z, a1.w * rB + bb1.w);
    float sum = v0.x + v0.y + v0.z + v0.w + v1.x + v1.y + v1.z + v1.w;
    float sq = v0.x * v0.x + v0.y * v0.y + v0.z * v0.z + v0.w * v0.w +
               v1.x * v1.x + v1.y * v1.y + v1.z * v1.z + v1.w * v1.w;
    sum = wredsum(sum);
    sq = wredsum(sq);
    float m = sum * (1.f / 256.f);
    float var = sq * (1.f / 256.f) - m * m;
    float inv = rsqrtf(var + 1e-5f);
    const float4* g4 = (const float4*)g;
    const float4* b4 = (const float4*)b2;
    float4 gg0 = g4[lane], gg1 = g4[32 + lane];
    float4 be0 = b4[lane], be1 = b4[32 + lane];
    float4 y0 = make_float4(elu1((v0.x - m) * inv * gg0.x + be0.x),
                            elu1((v0.y - m) * inv * gg0.y + be0.y),
                            elu1((v0.z - m) * inv * gg0.z + be0.z),
                            elu1((v0.w - m) * inv * gg0.w + be0.w));
    float4 y1 = make_float4(elu1((v1.x - m) * inv * gg1.x + be1.x),
                            elu1((v1.y - m) * inv * gg1.y + be1.y),
                            elu1((v1.z - m) * inv * gg1.z + be1.z),
                            elu1((v1.w - m) * inv * gg1.w + be1.w));
    float4* o4 = (float4*)d_hmid;
    o4[n * 64 + lane] = y0;
    o4[n * 64 + 32 + lane] = y1;
}

// transpose gat2 W: Wt[c][k] = W[k*64+c]
__global__ void k_wt(const float* __restrict__ W) {
    int idx = blockIdx.x * 256 + threadIdx.x;  // 16384
    int k = idx >> 6, c = idx & 63;
    d_wt[c * 256 + k] = W[idx];
}

// K5: gat2 linear h2 = hmid @ W(256,64) + attention scalars. 8 nodes/block.
__global__ void k_gat2_lin(const float* __restrict__ as_, const float* __restrict__ ad_) {
    __shared__ __align__(16) float sh[8][256];
    __shared__ __align__(16) float h2s[8][64];
    int t = threadIdx.x;
    int n0 = blockIdx.x * 8;
    const float4* hm = (const float4*)d_hmid;
    float4* shv = (float4*)sh;
    for (int i = t; i < 512; i += 256) shv[i] = hm[n0 * 64 + i];
    __syncthreads();
    int c = t & 63, grp = t >> 6;
    const float4* wt4 = (const float4*)&d_wt[c * 256];
    const float4* s0p = (const float4*)sh[grp];
    const float4* s1p = (const float4*)sh[grp + 4];
    float acc0 = 0.f, acc1 = 0.f;
#pragma unroll 8
    for (int k4 = 0; k4 < 64; k4++) {
        float4 w = wt4[k4];
        float4 s0 = s0p[k4];
        float4 s1 = s1p[k4];
        acc0 = fmaf(s0.x, w.x, fmaf(s0.y, w.y, fmaf(s0.z, w.z, fmaf(s0.w, w.w, acc0))));
        acc1 = fmaf(s1.x, w.x, fmaf(s1.y, w.y, fmaf(s1.z, w.z, fmaf(s1.w, w.w, acc1))));
    }
    h2s[grp][c] = acc0;
    h2s[grp + 4][c] = acc1;
    __syncthreads();
    int w = t >> 5, lane = t & 31;
    float2 h = ((float2*)h2s[w])[lane];
    ((float2*)d_h2)[(n0 + w) * 32 + lane] = h;
    float ps = wredsum(h.x * as_[2 * lane] + h.y * as_[2 * lane + 1]);
    float pd = wredsum(h.x * ad_[2 * lane] + h.y * ad_[2 * lane + 1]);
    if (lane == 0) { d_as2[n0 + w] = ps; d_ad2[n0 + w] = pd; }
}

// K6: GAT2 fused aggregate + LN(64) + identity + ELU + pool. Warp per node.
__global__ void k_agg2(const float* __restrict__ bias, const float* __restrict__ g,
                       const float* __restrict__ b2) {
    __shared__ float spool[64];
    int t = threadIdx.x, lane = t & 31, w = t >> 5;
    int n = blockIdx.x * 8 + w;
    if (t < 64) spool[t] = 0.f;
    __syncthreads();
    float adn = d_ad2[n];
    const float2* h2f = (const float2*)d_h2;
    float exs = expf(lrelu(d_as2[n] + adn));
    float2 hv = h2f[n * 32 + lane];
    float ax = exs * hv.x, ay = exs * hv.y;
    float den = exs;
    int s = d_off[n], e = d_off[n + 1];
    int srcN = (s < e) ? d_csrc[s] : 0;
#pragma unroll 1
    for (int i = s; i < e; i++) {
        int src = srcN;
        if (i + 1 < e) srcN = d_csrc[i + 1];
        float ex = expf(lrelu(d_as2[src] + adn));
        float2 v = h2f[src * 32 + lane];
        ax = fmaf(ex, v.x, ax);
        ay = fmaf(ex, v.y, ay);
        den += ex;
    }
    float r = 1.f / (den + 1e-16f);
    float v0 = ax * r + bias[2 * lane];
    float v1 = ay * r + bias[2 * lane + 1];
    float sum = wredsum(v0 + v1);
    float sq = wredsum(v0 * v0 + v1 * v1);
    float m = sum * (1.f / 64.f);
    float var = sq * (1.f / 64.f) - m * m;
    float inv = rsqrtf(var + 1e-5f);
    float y0 = elu1((v0 - m) * inv * g[2 * lane] + b2[2 * lane] + d_id[n * 64 + 2 * lane]);
    float y1 = elu1((v1 - m) * inv * g[2 * lane + 1] + b2[2 * lane + 1] + d_id[n * 64 + 2 * lane + 1]);
    atomicAdd(&spool[2 * lane], y0);
    atomicAdd(&spool[2 * lane + 1], y1);
    __syncthreads();
    if (t < 64) atomicAdd(&d_pool[t], spool[t]);
}

// K8: traffic encoder + fusion + final LN. Single block.
__global__ void k_final(const float* __restrict__ traffic, const float* __restrict__ trw,
                        const float* __restrict__ trb, const float* __restrict__ trg,
                        const float* __restrict__ trbe, const float* __restrict__ fuw,
                        const float* __restrict__ fub, const float* __restrict__ fug,
                        const float* __restrict__ fube, float* __restrict__ out) {
    int t = threadIdx.x, lane = t & 31, w = t >> 5;
    __shared__ float comb[96];
    __shared__ float rs[8], rq[8];
    if (t < 64) comb[t] = d_pool[t] * (1.f / (float)NN);
    if (t >= 128 && t < 160) {
        int c = t - 128;
        float v = trb[c];
#pragma unroll
        for (int k = 0; k < 5; k++) v = fmaf(traffic[k], trw[k * 32 + c], v);
        v = fmaxf(v, 0.f);
        float m = wredsum(v) * (1.f / 32.f);
        float d = v - m;
        float var = wredsum(d * d) * (1.f / 32.f);
        comb[64 + c] = d * rsqrtf(var + 1e-5f) * trg[c] + trbe[c];
    }
    __syncthreads();
    float o = fub[t];
#pragma unroll 8
    for (int k = 0; k < 96; k++) o = fmaf(comb[k], fuw[k * 256 + t], o);
    o = fmaxf(o, 0.f);
    float s = wredsum(o);
    float q = wredsum(o * o);
    if (lane == 0) { rs[w] = s; rq[w] = q; }
    __syncthreads();
    float S = 0.f, Q = 0.f;
#pragma unroll
    for (int i = 0; i < 8; i++) { S += rs[i]; Q += rq[i]; }
    float m = S * (1.f / 256.f);
    float var = Q * (1.f / 256.f) - m * m;
    out[t] = (o - m) * rsqrtf(var + 1e-5f) * fug[t] + fube[t];
}

extern "C" void kernel_launch(void* const* d_in, const int* in_sizes, int n_in,
                              void* d_out, int out_size) {
    bool dictOrder = (n_in > 3 && in_sizes[3] == 2 * EE);
    int ix[30];
    if (dictOrder) {
        for (int i = 0; i < 30; i++) ix[i] = i;
    } else {
        ix[0] = 0; ix[1] = 1; ix[2] = 2; ix[3] = n_in - 1;
        for (int i = 4; i < 30; i++) ix[i] = i - 1;
    }
    const float* pos    = (const float*)d_in[ix[0]];
    const float* deg    = (const float*)d_in[ix[1]];
    const float* tr     = (const float*)d_in[ix[2]];
    const int*   eiw    = (const int*)d_in[ix[3]];
    const float* enc_w  = (const float*)d_in[ix[4]];
    const float* enc_b  = (const float*)d_in[ix[5]];
    const float* enc_g  = (const float*)d_in[ix[6]];
    const float* enc_be = (const float*)d_in[ix[7]];
    const float* g1w    = (const float*)d_in[ix[8]];
    const float* g1as   = (const float*)d_in[ix[9]];
    const float* g1ad   = (const float*)d_in[ix[10]];
    const float* g1b    = (const float*)d_in[ix[11]];
    const float* n1g    = (const float*)d_in[ix[12]];
    const float* n1b    = (const float*)d_in[ix[13]];
    const float* pw     = (const float*)d_in[ix[14]];
    const float* pb     = (const float*)d_in[ix[15]];
    const float* g2w    = (const float*)d_in[ix[16]];
    const float* g2as   = (const float*)d_in[ix[17]];
    const float* g2ad   = (const float*)d_in[ix[18]];
    const float* g2b    = (const float*)d_in[ix[19]];
    const float* n2g    = (const float*)d_in[ix[20]];
    const float* n2b    = (const float*)d_in[ix[21]];
    const float* trw    = (const float*)d_in[ix[22]];
    const float* trb    = (const float*)d_in[ix[23]];
    const float* trg    = (const float*)d_in[ix[24]];
    const float* trbe   = (const float*)d_in[ix[25]];
    const float* fuw    = (const float*)d_in[ix[26]];
    const float* fub    = (const float*)d_in[ix[27]];
    const float* fug    = (const float*)d_in[ix[28]];
    const float* fube   = (const float*)d_in[ix[29]];

    k_detect<<<1, 32>>>(eiw);
    k_zero<<<(NN + 255) / 256, 256>>>();
    k_hist<<<EE / 256, 256>>>(eiw);
    k_scan<<<1, 1024>>>();
    k_scatter<<<EE / 256, 256>>>(eiw);
    k_encode<<<NN / 8, 256>>>(pos, deg, enc_w, enc_b, enc_g, enc_be);
    k_identity<<<NN / 4, 256>>>(pw, pb);
    k_gat1_lin<<<NN / 16, 256>>>(g1w, g1as, g1ad);
    k_agg1<<<NN / 8, 256>>>(g1b, n1g, n1b);
    k_wt<<<64, 256>>>(g2w);
    k_gat2_lin<<<NN / 8, 256>>>(g2as, g2ad);
    k_agg2<<<NN / 8, 256>>>(g2b, n2g, n2b);
    k_final<<<1, 256>>>(tr, trw, trb, trg, trbe, fuw, fub, fug, fube, (float*)d_out);
}

// round 4
// speedup vs baseline: 1.4423x; 1.0565x over previous
#include <cuda_runtime.h>

#define NN 50000
#define EE 800000
#define FULL 0xffffffffu
#define SCAN_BLOCKS 49

// ---- scratch (static device memory) ----
__device__ __align__(16) float d_x[NN * 32];
__device__ __align__(16) float d_id[NN * 64];
__device__ __align__(16) float d_h1[NN * 256];
__device__ __align__(16) float d_as1[NN * 4];
__device__ __align__(16) float d_ad1[NN * 4];
__device__ __align__(16) float d_hmid[NN * 256];
__device__ __align__(16) float d_h2[NN * 64];
__device__ __align__(16) float d_wt[64 * 256];
__device__ __align__(16) float d_was1[32 * 4];
__device__ __align__(16) float d_wad1[32 * 4];
__device__ float d_as2[NN];
__device__ float d_ad2[NN];
__device__ float d_pool[64];
__device__ int d_deg[NN];
__device__ int d_off[NN + 1];
__device__ int d_fill[NN];
__device__ int d_csrc[EE];
__device__ int d_bsum[SCAN_BLOCKS];
__device__ int d_boff[SCAN_BLOCKS];
__device__ int d_is64;

__device__ __forceinline__ float wredsum(float v) {
#pragma unroll
    for (int o = 16; o; o >>= 1) v += __shfl_xor_sync(FULL, v, o);
    return v;
}
__device__ __forceinline__ float lrelu(float x) { return x > 0.f ? x : 0.2f * x; }
__device__ __forceinline__ float elu1(float x) { return x > 0.f ? x : expm1f(x); }

// K0: detect edge_index dtype (int64 values < 50000 -> high words all zero).
__global__ void k_detect(const int* __restrict__ w) {
    if (threadIdx.x == 0) {
        int all0 = 1;
#pragma unroll 1
        for (int i = 0; i < 64; i++)
            if (w[2 * i + 1] != 0) { all0 = 0; break; }
        d_is64 = all0;
    }
}

__global__ void k_zero() {
    int i = blockIdx.x * 256 + threadIdx.x;
    if (i < NN) d_deg[i] = 0;
    if (i < 64) d_pool[i] = 0.f;
}

// fold attention vectors into weight space: was1[k][h] = sum_c W[k,h*64+c]*att_src[h,c]
__global__ void k_prep(const float* __restrict__ W, const float* __restrict__ as_,
                       const float* __restrict__ ad_) {
    int t = threadIdx.x;
    if (t < 128) {
        int k = t >> 2, h = t & 3;
        float sa = 0.f, sd = 0.f;
#pragma unroll 8
        for (int c = 0; c < 64; c++) {
            float w = W[k * 256 + h * 64 + c];
            sa = fmaf(w, as_[h * 64 + c], sa);
            sd = fmaf(w, ad_[h * 64 + c], sd);
        }
        d_was1[k * 4 + h] = sa;
        d_wad1[k * 4 + h] = sd;
    }
}

__global__ void k_hist(const int* __restrict__ eiw) {
    int e = blockIdx.x * 256 + threadIdx.x;
    int dst = d_is64 ? eiw[2 * (EE + e)] : eiw[EE + e];
    dst = min(max(dst, 0), NN - 1);
    atomicAdd(&d_deg[dst], 1);
}

// 3-phase scan: per-block scan -> block-sum scan -> add offsets.
__global__ void k_scan1() {
    __shared__ int ws[32];
    int t = threadIdx.x, lane = t & 31, wid = t >> 5;
    int i = blockIdx.x * 1024 + t;
    int v = (i < NN) ? d_deg[i] : 0;
    int x = v;
#pragma unroll
    for (int o = 1; o < 32; o <<= 1) {
        int y = __shfl_up_sync(FULL, x, o);
        if (lane >= o) x += y;
    }
    if (lane == 31) ws[wid] = x;
    __syncthreads();
    if (t < 32) {
        int s = ws[t];
#pragma unroll
        for (int o = 1; o < 32; o <<= 1) {
            int y = __shfl_up_sync(FULL, s, o);
            if (t >= o) s += y;
        }
        ws[t] = s;
    }
    __syncthreads();
    int excl = x - v + (wid > 0 ? ws[wid - 1] : 0);
    if (i < NN) d_off[i] = excl;
    if (t == 1023) d_bsum[blockIdx.x] = excl + v;
}

__global__ void k_scan2() {
    __shared__ int sh[64];
    int t = threadIdx.x;
    int v = (t < SCAN_BLOCKS) ? d_bsum[t] : 0;
    sh[t] = v;
    __syncthreads();
#pragma unroll
    for (int o = 1; o < 64; o <<= 1) {
        int y = (t >= o) ? sh[t - o] : 0;
        __syncthreads();
        sh[t] += y;
        __syncthreads();
    }
    if (t < SCAN_BLOCKS) d_boff[t] = sh[t] - v;
}

__global__ void k_scan3() {
    int i = blockIdx.x * 1024 + threadIdx.x;
    if (i < NN) {
        int o = d_off[i] + d_boff[blockIdx.x];
        d_off[i] = o;
        d_fill[i] = o;
    }
    if (i == 0) d_off[NN] = EE;
}

__global__ void k_scatter(const int* __restrict__ eiw) {
    int e = blockIdx.x * 256 + threadIdx.x;
    int src, dst;
    if (d_is64) { src = eiw[2 * e]; dst = eiw[2 * (EE + e)]; }
    else        { src = eiw[e];     dst = eiw[EE + e]; }
    src = min(max(src, 0), NN - 1);
    dst = min(max(dst, 0), NN - 1);
    int pos = atomicAdd(&d_fill[dst], 1);
    d_csrc[pos] = src;
}

// K1: node encoder Linear(4,32)+relu+LN(32), plus gat1 attention scalars
// via folded vectors (a_s = x @ was1). 8 nodes/block, 1 warp/node.
__global__ void k_encode(const float* __restrict__ pos, const float* __restrict__ deg,
                         const float* __restrict__ W, const float* __restrict__ b,
                         const float* __restrict__ g, const float* __restrict__ be) {
    int node = blockIdx.x * 8 + (threadIdx.x >> 5);
    int c = threadIdx.x & 31;
    float p0 = pos[node * 3], p1 = pos[node * 3 + 1], p2 = pos[node * 3 + 2], dgr = deg[node];
    float v = fmaf(p0, W[c], fmaf(p1, W[32 + c], fmaf(p2, W[64 + c], fmaf(dgr, W[96 + c], b[c]))));
    v = fmaxf(v, 0.f);
    float m = wredsum(v) * (1.f / 32.f);
    float d = v - m;
    float var = wredsum(d * d) * (1.f / 32.f);
    float xv = d * rsqrtf(var + 1e-5f) * g[c] + be[c];
    d_x[node * 32 + c] = xv;
    float4 wa = ((const float4*)d_was1)[c];
    float4 wd = ((const float4*)d_wad1)[c];
    float s0 = wredsum(xv * wa.x);
    float s1 = wredsum(xv * wa.y);
    float s2 = wredsum(xv * wa.z);
    float s3 = wredsum(xv * wa.w);
    float t0 = wredsum(xv * wd.x);
    float t1 = wredsum(xv * wd.y);
    float t2 = wredsum(xv * wd.z);
    float t3 = wredsum(xv * wd.w);
    if (c < 4) {
        d_as1[node * 4 + c] = c == 0 ? s0 : c == 1 ? s1 : c == 2 ? s2 : s3;
        d_ad1[node * 4 + c] = c == 0 ? t0 : c == 1 ? t1 : c == 2 ? t2 : t3;
    }
}

// K2: gat1 linear h1 = x@W (sync-free) + fused identity projection. 16 nodes/block.
__global__ void k_gat1_lin(const float* __restrict__ W, const float* __restrict__ pw,
                           const float* __restrict__ pb) {
    __shared__ float xs[16][32];
    int t = threadIdx.x;
    int n0 = blockIdx.x * 16;
    for (int i = t; i < 512; i += 256) xs[i >> 5][i & 31] = d_x[n0 * 32 + i];
    float wreg[32];
#pragma unroll
    for (int k = 0; k < 32; k++) wreg[k] = W[k * 256 + t];
    __syncthreads();
#pragma unroll 1
    for (int nn = 0; nn < 16; nn++) {
        float hv = 0.f;
#pragma unroll
        for (int k = 0; k < 32; k++) hv = fmaf(xs[nn][k], wreg[k], hv);
        d_h1[(n0 + nn) * 256 + t] = hv;
    }
    // identity: 64 channels x 16 nodes; thread covers channel c for 4 nodes
    int c = t & 63, gbase = t >> 6;
    float preg[32];
#pragma unroll
    for (int k = 0; k < 32; k++) preg[k] = pw[k * 64 + c];
    float pbc = pb[c];
#pragma unroll
    for (int gq = 0; gq < 4; gq++) {
        int nn = gbase + 4 * gq;
        float a = pbc;
#pragma unroll
        for (int k = 0; k < 32; k++) a = fmaf(xs[nn][k], preg[k], a);
        d_id[(n0 + nn) * 64 + c] = a;
    }
}

// K3: GAT1 fused aggregate + normalize + bias + LN(256) + ELU. Warp per node,
// software-pipelined gather (depth 2), per-lane head attention (no shfl chain).
__global__ void k_agg1(const float* __restrict__ bias, const float* __restrict__ g,
                       const float* __restrict__ b2) {
    int lane = threadIdx.x & 31;
    int n = blockIdx.x * 8 + (threadIdx.x >> 5);
    int hA = lane >> 4;  // head of first-half channels; second half head = 2+hA
    const float4* h4 = (const float4*)d_h1;

    float adA = d_ad1[n * 4 + hA];
    float adB = d_ad1[n * 4 + 2 + hA];
    // self-loop init
    float exA = expf(lrelu(d_as1[n * 4 + hA] + adA));
    float exB = expf(lrelu(d_as1[n * 4 + 2 + hA] + adB));
    float4 hv0 = h4[n * 64 + lane], hv1 = h4[n * 64 + 32 + lane];
    float4 a0 = make_float4(exA * hv0.x, exA * hv0.y, exA * hv0.z, exA * hv0.w);
    float4 a1 = make_float4(exB * hv1.x, exB * hv1.y, exB * hv1.z, exB * hv1.w);
    float denA = exA, denB = exB;

    int s = d_off[n], e = d_off[n + 1];
    // pipeline slots A (edge i), B (edge i+1)
    float asA0 = 0.f, asA1 = 0.f, asB0 = 0.f, asB1 = 0.f;
    float4 vA0 = make_float4(0, 0, 0, 0), vA1 = vA0, vB0 = vA0, vB1 = vA0;
    if (s < e) {
        int sc = d_csrc[s];
        asA0 = d_as1[sc * 4 + hA]; asA1 = d_as1[sc * 4 + 2 + hA];
        vA0 = h4[sc * 64 + lane];  vA1 = h4[sc * 64 + 32 + lane];
    }
    if (s + 1 < e) {
        int sc = d_csrc[s + 1];
        asB0 = d_as1[sc * 4 + hA]; asB1 = d_as1[sc * 4 + 2 + hA];
        vB0 = h4[sc * 64 + lane];  vB1 = h4[sc * 64 + 32 + lane];
    }
#pragma unroll 1
    for (int i = s; i < e; i++) {
        float asN0 = 0.f, asN1 = 0.f;
        float4 vN0 = make_float4(0, 0, 0, 0), vN1 = vN0;
        if (i + 2 < e) {
            int sc = d_csrc[i + 2];
            asN0 = d_as1[sc * 4 + hA]; asN1 = d_as1[sc * 4 + 2 + hA];
            vN0 = h4[sc * 64 + lane];  vN1 = h4[sc * 64 + 32 + lane];
        }
        float eA = expf(lrelu(asA0 + adA));
        float eB = expf(lrelu(asA1 + adB));
        a0.x = fmaf(eA, vA0.x, a0.x); a0.y = fmaf(eA, vA0.y, a0.y);
        a0.z = fmaf(eA, vA0.z, a0.z); a0.w = fmaf(eA, vA0.w, a0.w);
        a1.x = fmaf(eB, vA1.x, a1.x); a1.y = fmaf(eB, vA1.y, a1.y);
        a1.z = fmaf(eB, vA1.z, a1.z); a1.w = fmaf(eB, vA1.w, a1.w);
        denA += eA; denB += eB;
        asA0 = asB0; asA1 = asB1; vA0 = vB0; vA1 = vB1;
        asB0 = asN0; asB1 = asN1; vB0 = vN0; vB1 = vN1;
    }
    float rA = 1.f / (denA + 1e-16f), rB = 1.f / (denB + 1e-16f);
    const float4* bi4 = (const float4*)bias;
    float4 bb0 = bi4[lane], bb1 = bi4[32 + lane];
    float4 v0 = make_float4(a0.x * rA + bb0.x, a0.y * rA + bb0.y,
                            a0.z * rA + bb0.z, a0.w * rA + bb0.w);
    float4 v1 = make_float4(a1.x * rB + bb1.x, a1.y * rB + bb1.y,
                            a1.z * rB + bb1.z, a1.w * rB + bb1.w);
    float sum = v0.x + v0.y + v0.z + v0.w + v1.x + v1.y + v1.z + v1.w;
    float sq = v0.x * v0.x + v0.y * v0.y + v0.z * v0.z + v0.w * v0.w +
               v1.x * v1.x + v1.y * v1.y + v1.z * v1.z + v1.w * v1.w;
    sum = wredsum(sum);
    sq = wredsum(sq);
    float m = sum * (1.f / 256.f);
    float var = sq * (1.f / 256.f) - m * m;
    float inv = rsqrtf(var + 1e-5f);
    const float4* g4 = (const float4*)g;
    const float4* b4 = (const float4*)b2;
    float4 gg0 = g4[lane], gg1 = g4[32 + lane];
    float4 be0 = b4[lane], be1 = b4[32 + lane];
    float4 y0 = make_float4(elu1((v0.x - m) * inv * gg0.x + be0.x),
                            elu1((v0.y - m) * inv * gg0.y + be0.y),
                            elu1((v0.z - m) * inv * gg0.z + be0.z),
                            elu1((v0.w - m) * inv * gg0.w + be0.w));
    float4 y1 = make_float4(elu1((v1.x - m) * inv * gg1.x + be1.x),
                            elu1((v1.y - m) * inv * gg1.y + be1.y),
                            elu1((v1.z - m) * inv * gg1.z + be1.z),
                            elu1((v1.w - m) * inv * gg1.w + be1.w));
    float4* o4 = (float4*)d_hmid;
    o4[n * 64 + lane] = y0;
    o4[n * 64 + 32 + lane] = y1;
}

// transpose gat2 W: Wt[c][k] = W[k*64+c]
__global__ void k_wt(const float* __restrict__ W) {
    int idx = blockIdx.x * 256 + threadIdx.x;  // 16384
    int k = idx >> 6, c = idx & 63;
    d_wt[c * 256 + k] = W[idx];
}

// K5: gat2 linear h2 = hmid @ W(256,64) + attention scalars. 8 nodes/block.
__global__ void k_gat2_lin(const float* __restrict__ as_, const float* __restrict__ ad_) {
    __shared__ __align__(16) float sh[8][256];
    __shared__ __align__(16) float h2s[8][64];
    int t = threadIdx.x;
    int n0 = blockIdx.x * 8;
    const float4* hm = (const float4*)d_hmid;
    float4* shv = (float4*)sh;
    for (int i = t; i < 512; i += 256) shv[i] = hm[n0 * 64 + i];
    __syncthreads();
    int c = t & 63, grp = t >> 6;
    const float4* wt4 = (const float4*)&d_wt[c * 256];
    const float4* s0p = (const float4*)sh[grp];
    const float4* s1p = (const float4*)sh[grp + 4];
    float acc0 = 0.f, acc1 = 0.f;
#pragma unroll 8
    for (int k4 = 0; k4 < 64; k4++) {
        float4 w = wt4[k4];
        float4 s0 = s0p[k4];
        float4 s1 = s1p[k4];
        acc0 = fmaf(s0.x, w.x, fmaf(s0.y, w.y, fmaf(s0.z, w.z, fmaf(s0.w, w.w, acc0))));
        acc1 = fmaf(s1.x, w.x, fmaf(s1.y, w.y, fmaf(s1.z, w.z, fmaf(s1.w, w.w, acc1))));
    }
    h2s[grp][c] = acc0;
    h2s[grp + 4][c] = acc1;
    __syncthreads();
    int w = t >> 5, lane = t & 31;
    float2 h = ((float2*)h2s[w])[lane];
    ((float2*)d_h2)[(n0 + w) * 32 + lane] = h;
    float ps = wredsum(h.x * as_[2 * lane] + h.y * as_[2 * lane + 1]);
    float pd = wredsum(h.x * ad_[2 * lane] + h.y * ad_[2 * lane + 1]);
    if (lane == 0) { d_as2[n0 + w] = ps; d_ad2[n0 + w] = pd; }
}

// K6: GAT2 fused aggregate + LN(64) + identity + ELU + pool. Warp per node,
// depth-3 software pipeline.
__global__ void k_agg2(const float* __restrict__ bias, const float* __restrict__ g,
                       const float* __restrict__ b2) {
    __shared__ float spool[64];
    int t = threadIdx.x, lane = t & 31, w = t >> 5;
    int n = blockIdx.x * 8 + w;
    if (t < 64) spool[t] = 0.f;
    __syncthreads();
    float adn = d_ad2[n];
    const float2* h2f = (const float2*)d_h2;
    float exs = expf(lrelu(d_as2[n] + adn));
    float2 hv = h2f[n * 32 + lane];
    float ax = exs * hv.x, ay = exs * hv.y;
    float den = exs;
    int s = d_off[n], e = d_off[n + 1];
    float asA = 0.f, asB = 0.f, asC = 0.f;
    float2 vA = make_float2(0, 0), vB = vA, vC = vA;
    if (s < e)     { int sc = d_csrc[s];     asA = d_as2[sc]; vA = h2f[sc * 32 + lane]; }
    if (s + 1 < e) { int sc = d_csrc[s + 1]; asB = d_as2[sc]; vB = h2f[sc * 32 + lane]; }
    if (s + 2 < e) { int sc = d_csrc[s + 2]; asC = d_as2[sc]; vC = h2f[sc * 32 + lane]; }
#pragma unroll 1
    for (int i = s; i < e; i++) {
        float asN = 0.f;
        float2 vN = make_float2(0, 0);
        if (i + 3 < e) { int sc = d_csrc[i + 3]; asN = d_as2[sc]; vN = h2f[sc * 32 + lane]; }
        float ex = expf(lrelu(asA + adn));
        ax = fmaf(ex, vA.x, ax);
        ay = fmaf(ex, vA.y, ay);
        den += ex;
        asA = asB; vA = vB;
        asB = asC; vB = vC;
        asC = asN; vC = vN;
    }
    float r = 1.f / (den + 1e-16f);
    float v0 = ax * r + bias[2 * lane];
    float v1 = ay * r + bias[2 * lane + 1];
    float sum = wredsum(v0 + v1);
    float sq = wredsum(v0 * v0 + v1 * v1);
    float m = sum * (1.f / 64.f);
    float var = sq * (1.f / 64.f) - m * m;
    float inv = rsqrtf(var + 1e-5f);
    float y0 = elu1((v0 - m) * inv * g[2 * lane] + b2[2 * lane] + d_id[n * 64 + 2 * lane]);
    float y1 = elu1((v1 - m) * inv * g[2 * lane + 1] + b2[2 * lane + 1] + d_id[n * 64 + 2 * lane + 1]);
    atomicAdd(&spool[2 * lane], y0);
    atomicAdd(&spool[2 * lane + 1], y1);
    __syncthreads();
    if (t < 64) atomicAdd(&d_pool[t], spool[t]);
}

// K8: traffic encoder + fusion + final LN. Single block.
__global__ void k_final(const float* __restrict__ traffic, const float* __restrict__ trw,
                        const float* __restrict__ trb, const float* __restrict__ trg,
                        const float* __restrict__ trbe, const float* __restrict__ fuw,
                        const float* __restrict__ fub, const float* __restrict__ fug,
                        const float* __restrict__ fube, float* __restrict__ out) {
    int t = threadIdx.x, lane = t & 31, w = t >> 5;
    __shared__ float comb[96];
    __shared__ float rs[8], rq[8];
    if (t < 64) comb[t] = d_pool[t] * (1.f / (float)NN);
    if (t >= 128 && t < 160) {
        int c = t - 128;
        float v = trb[c];
#pragma unroll
        for (int k = 0; k < 5; k++) v = fmaf(traffic[k], trw[k * 32 + c], v);
        v = fmaxf(v, 0.f);
        float m = wredsum(v) * (1.f / 32.f);
        float d = v - m;
        float var = wredsum(d * d) * (1.f / 32.f);
        comb[64 + c] = d * rsqrtf(var + 1e-5f) * trg[c] + trbe[c];
    }
    __syncthreads();
    float o = fub[t];
#pragma unroll 8
    for (int k = 0; k < 96; k++) o = fmaf(comb[k], fuw[k * 256 + t], o);
    o = fmaxf(o, 0.f);
    float s = wredsum(o);
    float q = wredsum(o * o);
    if (lane == 0) { rs[w] = s; rq[w] = q; }
    __syncthreads();
    float S = 0.f, Q = 0.f;
#pragma unroll
    for (int i = 0; i < 8; i++) { S += rs[i]; Q += rq[i]; }
    float m = S * (1.f / 256.f);
    float var = Q * (1.f / 256.f) - m * m;
    out[t] = (o - m) * rsqrtf(var + 1e-5f) * fug[t] + fube[t];
}

extern "C" void kernel_launch(void* const* d_in, const int* in_sizes, int n_in,
                              void* d_out, int out_size) {
    bool dictOrder = (n_in > 3 && in_sizes[3] == 2 * EE);
    int ix[30];
    if (dictOrder) {
        for (int i = 0; i < 30; i++) ix[i] = i;
    } else {
        ix[0] = 0; ix[1] = 1; ix[2] = 2; ix[3] = n_in - 1;
        for (int i = 4; i < 30; i++) ix[i] = i - 1;
    }
    const float* pos    = (const float*)d_in[ix[0]];
    const float* deg    = (const float*)d_in[ix[1]];
    const float* tr     = (const float*)d_in[ix[2]];
    const int*   eiw    = (const int*)d_in[ix[3]];
    const float* enc_w  = (const float*)d_in[ix[4]];
    const float* enc_b  = (const float*)d_in[ix[5]];
    const float* enc_g  = (const float*)d_in[ix[6]];
    const float* enc_be = (const float*)d_in[ix[7]];
    const float* g1w    = (const float*)d_in[ix[8]];
    const float* g1as   = (const float*)d_in[ix[9]];
    const float* g1ad   = (const float*)d_in[ix[10]];
    const float* g1b    = (const float*)d_in[ix[11]];
    const float* n1g    = (const float*)d_in[ix[12]];
    const float* n1b    = (const float*)d_in[ix[13]];
    const float* pw     = (const float*)d_in[ix[14]];
    const float* pb     = (const float*)d_in[ix[15]];
    const float* g2w    = (const float*)d_in[ix[16]];
    const float* g2as   = (const float*)d_in[ix[17]];
    const float* g2ad   = (const float*)d_in[ix[18]];
    const float* g2b    = (const float*)d_in[ix[19]];
    const float* n2g    = (const float*)d_in[ix[20]];
    const float* n2b    = (const float*)d_in[ix[21]];
    const float* trw    = (const float*)d_in[ix[22]];
    const float* trb    = (const float*)d_in[ix[23]];
    const float* trg    = (const float*)d_in[ix[24]];
    const float* trbe   = (const float*)d_in[ix[25]];
    const float* fuw    = (const float*)d_in[ix[26]];
    const float* fub    = (const float*)d_in[ix[27]];
    const float* fug    = (const float*)d_in[ix[28]];
    const float* fube   = (const float*)d_in[ix[29]];

    k_detect<<<1, 32>>>(eiw);
    k_zero<<<(NN + 255) / 256, 256>>>();
    k_prep<<<1, 128>>>(g1w, g1as, g1ad);
    k_hist<<<EE / 256, 256>>>(eiw);
    k_scan1<<<SCAN_BLOCKS, 1024>>>();
    k_scan2<<<1, 64>>>();
    k_scan3<<<SCAN_BLOCKS, 1024>>>();
    k_scatter<<<EE / 256, 256>>>(eiw);
    k_encode<<<NN / 8, 256>>>(pos, deg, enc_w, enc_b, enc_g, enc_be);
    k_gat1_lin<<<NN / 16, 256>>>(g1w, pw, pb);
    k_agg1<<<NN / 8, 256>>>(g1b, n1g, n1b);
    k_wt<<<64, 256>>>(g2w);
    k_gat2_lin<<<NN / 8, 256>>>(g2as, g2ad);
    k_agg2<<<NN / 8, 256>>>(g2b, n2g, n2b);
    k_final<<<1, 256>>>(tr, trw, trb, trg, trbe, fuw, fub, fug, fube, (float*)d_out);
}